// round 1
// baseline (speedup 1.0000x reference)
#include <cuda_runtime.h>
#include <cuda_bf16.h>

// Problem constants (match reference_code)
#define NN 100000
#define EE 1600000
#define ET (EE + NN)          // edges + self loops = 1,700,000
#define IN_DIM 128
#define HID 32
#define NEG_SLOPE 0.2f

// ---------------- scratch (__device__ globals; no allocation allowed) ------
__device__ float    g_xl[NN * 32];
__device__ float    g_xr[NN * 32];
__device__ float    g_h [NN * 32];   // layer-1 output (pre-ReLU + bias)
__device__ float    g_s [ET];        // edge scores, then p = exp(s - m)
__device__ unsigned g_m [NN];        // encoded segment max
__device__ float    g_z [NN];        // segment sum of p
__device__ float    g_cnt  [NN];
__device__ float    g_mattr[NN];     // sum, then mean of incoming edge_attr

// ---------------- helpers --------------------------------------------------
__device__ __forceinline__ unsigned enc_f(float f) {
    unsigned u = __float_as_uint(f);
    return (u & 0x80000000u) ? ~u : (u | 0x80000000u);
}
__device__ __forceinline__ float dec_f(unsigned u) {
    return (u & 0x80000000u) ? __uint_as_float(u & 0x7FFFFFFFu)
                             : __uint_as_float(~u);
}

// ---------------- prologue: self-loop fill_value='mean' --------------------
__global__ void k_zero_cnt() {
    int i = blockIdx.x * blockDim.x + threadIdx.x;
    if (i < NN) { g_cnt[i] = 0.f; g_mattr[i] = 0.f; }
}
__global__ void k_accum_cnt(const int* __restrict__ dst,
                            const float* __restrict__ ea) {
    int e = blockIdx.x * blockDim.x + threadIdx.x;
    if (e < EE) {
        int d = dst[e];
        atomicAdd(&g_cnt[d], 1.0f);
        atomicAdd(&g_mattr[d], ea[e]);
    }
}
__global__ void k_mean() {
    int i = blockIdx.x * blockDim.x + threadIdx.x;
    if (i < NN) g_mattr[i] = g_mattr[i] / fmaxf(g_cnt[i], 1.0f);
}

// ---------------- linear transforms ---------------------------------------
// Layer 1: x (N x 128) -> xl, xr (N x 32). Warp per row, W staged in smem.
__global__ void k_transform128(const float* __restrict__ x,
                               const float* __restrict__ Wl, const float* __restrict__ bl,
                               const float* __restrict__ Wr, const float* __restrict__ br) {
    __shared__ float sWl[IN_DIM * 32];
    __shared__ float sWr[IN_DIM * 32];
    __shared__ float srow[8][IN_DIM];
    int tid = threadIdx.x;
    for (int i = tid; i < IN_DIM * 32; i += 256) { sWl[i] = Wl[i]; sWr[i] = Wr[i]; }
    __syncthreads();
    int warp = tid >> 5, lane = tid & 31;
    int r = blockIdx.x * 8 + warp;
    if (r >= NN) return;
    for (int k = lane; k < IN_DIM; k += 32) srow[warp][k] = x[r * IN_DIM + k];
    __syncwarp();
    float accl = bl[lane], accr = br[lane];
#pragma unroll
    for (int k = 0; k < IN_DIM; k++) {
        float xv = srow[warp][k];
        accl = fmaf(xv, sWl[k * 32 + lane], accl);
        accr = fmaf(xv, sWr[k * 32 + lane], accr);
    }
    g_xl[r * 32 + lane] = accl;
    g_xr[r * 32 + lane] = accr;
}

// Layer 2: h (N x 32, ReLU applied on read) -> xl, xr (N x 32). Warp per row.
__global__ void k_transform32(const float* __restrict__ Wl, const float* __restrict__ bl,
                              const float* __restrict__ Wr, const float* __restrict__ br) {
    __shared__ float sWl[32 * 32];
    __shared__ float sWr[32 * 32];
    int tid = threadIdx.x;
    for (int i = tid; i < 32 * 32; i += 256) { sWl[i] = Wl[i]; sWr[i] = Wr[i]; }
    __syncthreads();
    int warp = tid >> 5, lane = tid & 31;
    int r = blockIdx.x * 8 + warp;
    if (r >= NN) return;
    float hv = fmaxf(g_h[r * 32 + lane], 0.0f);   // ReLU folded here
    float accl = bl[lane], accr = br[lane];
#pragma unroll
    for (int k = 0; k < 32; k++) {
        float xv = __shfl_sync(0xFFFFFFFFu, hv, k);
        accl = fmaf(xv, sWl[k * 32 + lane], accl);
        accr = fmaf(xv, sWr[k * 32 + lane], accr);
    }
    g_xl[r * 32 + lane] = accl;
    g_xr[r * 32 + lane] = accr;
}

// ---------------- softmax state init + output=bias -------------------------
__global__ void k_init_layer(float* __restrict__ out, const float* __restrict__ b) {
    int idx = blockIdx.x * blockDim.x + threadIdx.x;
    if (idx < NN * 32) out[idx] = b[idx & 31];
    if (idx < NN) { g_m[idx] = 0u; g_z[idx] = 0.f; }
}

// ---------------- edge scores + segment max (warp per edge) ----------------
__global__ void k_scores(const int* __restrict__ src, const int* __restrict__ dst,
                         const float* __restrict__ ea,
                         const float* __restrict__ We, const float* __restrict__ att) {
    int e = blockIdx.x * 8 + (threadIdx.x >> 5);
    int lane = threadIdx.x & 31;
    if (e >= ET) return;
    int sN, dN; float a;
    if (e < EE) { sN = src[e]; dN = dst[e]; a = ea[e]; }
    else        { sN = dN = e - EE;         a = g_mattr[e - EE]; }
    float v = g_xl[sN * 32 + lane] + g_xr[dN * 32 + lane] + a * We[lane];
    v = (v > 0.f) ? v : NEG_SLOPE * v;
    v *= att[lane];
#pragma unroll
    for (int o = 16; o > 0; o >>= 1) v += __shfl_xor_sync(0xFFFFFFFFu, v, o);
    if (lane == 0) {
        g_s[e] = v;
        atomicMax(&g_m[dN], enc_f(v));
    }
}

// ---------------- p = exp(s - m[dst]); z += p (thread per edge) -------------
__global__ void k_expsum(const int* __restrict__ dst) {
    int e = blockIdx.x * blockDim.x + threadIdx.x;
    if (e >= ET) return;
    int dN = (e < EE) ? dst[e] : (e - EE);
    float p = expf(g_s[e] - dec_f(g_m[dN]));
    g_s[e] = p;
    atomicAdd(&g_z[dN], p);
}

// ---------------- out[dst] += (p/z[dst]) * xl[src] (warp per edge) ----------
__global__ void k_aggregate(const int* __restrict__ src, const int* __restrict__ dst,
                            float* __restrict__ out) {
    int e = blockIdx.x * 8 + (threadIdx.x >> 5);
    int lane = threadIdx.x & 31;
    if (e >= ET) return;
    int sN, dN;
    if (e < EE) { sN = src[e]; dN = dst[e]; }
    else        { sN = dN = e - EE; }
    float alpha = g_s[e] / g_z[dN];
    atomicAdd(&out[dN * 32 + lane], alpha * g_xl[sN * 32 + lane]);
}

// ---------------- launch ----------------------------------------------------
extern "C" void kernel_launch(void* const* d_in, const int* in_sizes, int n_in,
                              void* d_out, int out_size) {
    const float* x    = (const float*)d_in[0];
    const int*   src  = (const int*)  d_in[1];
    const int*   dst  = (const int*)  d_in[2];
    const float* ea   = (const float*)d_in[3];
    const float* Wl1  = (const float*)d_in[4];
    const float* bl1  = (const float*)d_in[5];
    const float* Wr1  = (const float*)d_in[6];
    const float* br1  = (const float*)d_in[7];
    const float* We1  = (const float*)d_in[8];
    const float* att1 = (const float*)d_in[9];
    const float* b1   = (const float*)d_in[10];
    const float* Wl2  = (const float*)d_in[11];
    const float* bl2  = (const float*)d_in[12];
    const float* Wr2  = (const float*)d_in[13];
    const float* br2  = (const float*)d_in[14];
    const float* We2  = (const float*)d_in[15];
    const float* att2 = (const float*)d_in[16];
    const float* b2   = (const float*)d_in[17];
    float* out = (float*)d_out;

    float* h_ptr = nullptr;
    cudaGetSymbolAddress((void**)&h_ptr, g_h);  // host-side, not captured as work

    const int T = 256;
    int gN   = (NN + T - 1) / T;          // per-node, thread-per-node
    int gN32 = (NN * 32 + T - 1) / T;     // per node-feature
    int gE   = (EE + T - 1) / T;          // per original edge
    int gEt  = (ET + T - 1) / T;          // per total edge, thread-per-edge
    int gEw  = (ET + 7) / 8;              // per total edge, warp-per-edge
    int gRow = (NN + 7) / 8;              // warp-per-row

    // self-loop mean edge_attr
    k_zero_cnt <<<gN, T>>>();
    k_accum_cnt<<<gE, T>>>(dst, ea);
    k_mean     <<<gN, T>>>();

    // ---- layer 1 ----
    k_transform128<<<gRow, T>>>(x, Wl1, bl1, Wr1, br1);
    k_init_layer  <<<gN32, T>>>(h_ptr, b1);
    k_scores      <<<gEw, T>>>(src, dst, ea, We1, att1);
    k_expsum      <<<gEt, T>>>(dst);
    k_aggregate   <<<gEw, T>>>(src, dst, h_ptr);

    // ---- layer 2 (ReLU folded into transform read) ----
    k_transform32<<<gRow, T>>>(Wl2, bl2, Wr2, br2);
    k_init_layer <<<gN32, T>>>(out, b2);
    k_scores     <<<gEw, T>>>(src, dst, ea, We2, att2);
    k_expsum     <<<gEt, T>>>(dst);
    k_aggregate  <<<gEw, T>>>(src, dst, out);
}

// round 3
// speedup vs baseline: 2.4515x; 2.4515x over previous
#include <cuda_runtime.h>
#include <cuda_bf16.h>

// Problem constants (match reference_code)
#define NN 100000
#define EE 1600000
#define ET (EE + NN)          // edges + self loops = 1,700,000
#define IN_DIM 128
#define NEG_SLOPE 0.2f

// ---------------- scratch (__device__ globals; no allocation allowed) ------
__device__ float    g_xl[NN * 32];
__device__ float    g_xr[NN * 32];
__device__ float    g_h [NN * 32];   // layer-1 output
__device__ float    g_s [ET];        // edge scores
__device__ unsigned g_m [NN];        // encoded segment max
__device__ float    g_z [NN];        // segment sum of p
__device__ float    g_cnt  [NN];
__device__ float    g_mattr[NN];     // sum -> mean of incoming edge_attr

// ---------------- helpers --------------------------------------------------
__device__ __forceinline__ unsigned enc_f(float f) {
    unsigned u = __float_as_uint(f);
    return (u & 0x80000000u) ? ~u : (u | 0x80000000u);
}
__device__ __forceinline__ float dec_f(unsigned u) {
    return (u & 0x80000000u) ? __uint_as_float(u & 0x7FFFFFFFu)
                             : __uint_as_float(~u);
}
__device__ __forceinline__ void red_add_v4(float* p, float a, float b, float c, float d) {
    asm volatile("red.global.add.v4.f32 [%0], {%1,%2,%3,%4};"
                 :: "l"(p), "f"(a), "f"(b), "f"(c), "f"(d) : "memory");
}

// ---------------- prologue: self-loop fill_value='mean' --------------------
__global__ void k_zero_cnt() {
    int i = blockIdx.x * blockDim.x + threadIdx.x;
    if (i < NN) { g_cnt[i] = 0.f; g_mattr[i] = 0.f; }
}
__global__ void k_accum_cnt(const int* __restrict__ dst,
                            const float* __restrict__ ea) {
    int e = blockIdx.x * blockDim.x + threadIdx.x;
    if (e < EE) {
        int d = dst[e];
        atomicAdd(&g_cnt[d], 1.0f);
        atomicAdd(&g_mattr[d], ea[e]);
    }
}
__global__ void k_mean() {
    int i = blockIdx.x * blockDim.x + threadIdx.x;
    if (i < NN) g_mattr[i] = g_mattr[i] / fmaxf(g_cnt[i], 1.0f);
}

// ---------------- linear transforms ---------------------------------------
// Layer 1: x (N x 128) -> xl, xr (N x 32).
// 4 rows per warp, x rows in float4 registers, W staged in smem and each W
// load amortized over 4 rows (register blocking kills the LDS bottleneck).
__global__ void k_transform128(const float* __restrict__ x,
                               const float* __restrict__ Wl, const float* __restrict__ bl,
                               const float* __restrict__ Wr, const float* __restrict__ br) {
    __shared__ float sWl[IN_DIM * 32];
    __shared__ float sWr[IN_DIM * 32];
    int tid = threadIdx.x;
    for (int i = tid; i < IN_DIM * 32; i += 256) { sWl[i] = Wl[i]; sWr[i] = Wr[i]; }
    __syncthreads();
    int warp = tid >> 5, lane = tid & 31;
    int r0 = (blockIdx.x * 8 + warp) * 4;          // 4 rows per warp
    if (r0 >= NN) return;

    float4 xv[4];
#pragma unroll
    for (int j = 0; j < 4; j++)
        xv[j] = ((const float4*)x)[(r0 + j) * 32 + lane];  // row element lane*4+c

    float blv = bl[lane], brv = br[lane];
    float accl[4], accr[4];
#pragma unroll
    for (int j = 0; j < 4; j++) { accl[j] = blv; accr[j] = brv; }

    for (int c = 0; c < 32; c++) {                 // k = c*4 + cc, src lane = c
#pragma unroll
        for (int cc = 0; cc < 4; cc++) {
            int k = c * 4 + cc;
            float wl = sWl[k * 32 + lane];
            float wr = sWr[k * 32 + lane];
#pragma unroll
            for (int j = 0; j < 4; j++) {
                float srcv = (cc == 0) ? xv[j].x : (cc == 1) ? xv[j].y
                           : (cc == 2) ? xv[j].z : xv[j].w;
                float xk = __shfl_sync(0xFFFFFFFFu, srcv, c);
                accl[j] = fmaf(xk, wl, accl[j]);
                accr[j] = fmaf(xk, wr, accr[j]);
            }
        }
    }
#pragma unroll
    for (int j = 0; j < 4; j++) {
        g_xl[(r0 + j) * 32 + lane] = accl[j];
        g_xr[(r0 + j) * 32 + lane] = accr[j];
    }
}

// Layer 2: h (N x 32, ReLU on read) -> xl, xr (N x 32). Warp per row.
__global__ void k_transform32(const float* __restrict__ Wl, const float* __restrict__ bl,
                              const float* __restrict__ Wr, const float* __restrict__ br) {
    __shared__ float sWl[32 * 32];
    __shared__ float sWr[32 * 32];
    int tid = threadIdx.x;
    for (int i = tid; i < 32 * 32; i += 256) { sWl[i] = Wl[i]; sWr[i] = Wr[i]; }
    __syncthreads();
    int warp = tid >> 5, lane = tid & 31;
    int r = blockIdx.x * 8 + warp;
    if (r >= NN) return;
    float hv = fmaxf(g_h[r * 32 + lane], 0.0f);   // ReLU folded here
    float accl = bl[lane], accr = br[lane];
#pragma unroll
    for (int k = 0; k < 32; k++) {
        float xv = __shfl_sync(0xFFFFFFFFu, hv, k);
        accl = fmaf(xv, sWl[k * 32 + lane], accl);
        accr = fmaf(xv, sWr[k * 32 + lane], accr);
    }
    g_xl[r * 32 + lane] = accl;
    g_xr[r * 32 + lane] = accr;
}

// ---------------- init: out=0, m=0(enc -inf), z=0 --------------------------
__global__ void k_init_layer(float* __restrict__ out) {
    int idx = blockIdx.x * blockDim.x + threadIdx.x;
    if (idx < NN * 8) ((float4*)out)[idx] = make_float4(0.f, 0.f, 0.f, 0.f);
    if (idx < NN) { g_m[idx] = 0u; g_z[idx] = 0.f; }
}

// ---------------- edge scores + segment max --------------------------------
// 4 edges per warp; 8 lanes (float4 each) per edge.
__global__ void k_scores(const int* __restrict__ src, const int* __restrict__ dst,
                         const float* __restrict__ ea,
                         const float* __restrict__ We, const float* __restrict__ att) {
    int warp = (blockIdx.x * blockDim.x + threadIdx.x) >> 5;
    int lane = threadIdx.x & 31;
    int e = warp * 4 + (lane >> 3);
    int q = lane & 7;
    if (e >= ET) return;
    int sN, dN; float a;
    if (e < EE) { sN = src[e]; dN = dst[e]; a = ea[e]; }
    else        { sN = dN = e - EE;         a = g_mattr[e - EE]; }

    float4 xl4 = ((const float4*)g_xl)[sN * 8 + q];
    float4 xr4 = ((const float4*)g_xr)[dN * 8 + q];
    float4 we4 = ((const float4*)We)[q];
    float4 at4 = ((const float4*)att)[q];

    float t, v = 0.f;
    t = xl4.x + xr4.x + a * we4.x; t = (t > 0.f) ? t : NEG_SLOPE * t; v = fmaf(t, at4.x, v);
    t = xl4.y + xr4.y + a * we4.y; t = (t > 0.f) ? t : NEG_SLOPE * t; v = fmaf(t, at4.y, v);
    t = xl4.z + xr4.z + a * we4.z; t = (t > 0.f) ? t : NEG_SLOPE * t; v = fmaf(t, at4.z, v);
    t = xl4.w + xr4.w + a * we4.w; t = (t > 0.f) ? t : NEG_SLOPE * t; v = fmaf(t, at4.w, v);

    v += __shfl_xor_sync(0xFFFFFFFFu, v, 1);
    v += __shfl_xor_sync(0xFFFFFFFFu, v, 2);
    v += __shfl_xor_sync(0xFFFFFFFFu, v, 4);
    if (q == 0) {
        g_s[e] = v;
        atomicMax(&g_m[dN], enc_f(v));
    }
}

// ---------------- fused exp + z-accum + unnormalized aggregate -------------
// out[dst] += p * xl[src],  z[dst] += p,  p = exp(s - m[dst]).
__global__ void k_aggregate(const int* __restrict__ src, const int* __restrict__ dst,
                            float* __restrict__ out) {
    int warp = (blockIdx.x * blockDim.x + threadIdx.x) >> 5;
    int lane = threadIdx.x & 31;
    int e = warp * 4 + (lane >> 3);
    int q = lane & 7;
    if (e >= ET) return;
    int sN, dN;
    if (e < EE) { sN = src[e]; dN = dst[e]; }
    else        { sN = dN = e - EE; }

    float p = expf(g_s[e] - dec_f(g_m[dN]));
    if (q == 0) atomicAdd(&g_z[dN], p);
    float4 xl4 = ((const float4*)g_xl)[sN * 8 + q];
    red_add_v4(out + dN * 32 + q * 4, p * xl4.x, p * xl4.y, p * xl4.z, p * xl4.w);
}

// ---------------- normalize: out = out/z + bias ----------------------------
__global__ void k_norm(float* __restrict__ out, const float* __restrict__ b) {
    int idx = blockIdx.x * blockDim.x + threadIdx.x;
    if (idx >= NN * 8) return;
    int n = idx >> 3, fq = idx & 7;
    float zin = 1.0f / g_z[n];
    float4 v = ((float4*)out)[idx];
    float4 b4 = ((const float4*)b)[fq];
    v.x = fmaf(v.x, zin, b4.x);
    v.y = fmaf(v.y, zin, b4.y);
    v.z = fmaf(v.z, zin, b4.z);
    v.w = fmaf(v.w, zin, b4.w);
    ((float4*)out)[idx] = v;
}

// ---------------- launch ----------------------------------------------------
extern "C" void kernel_launch(void* const* d_in, const int* in_sizes, int n_in,
                              void* d_out, int out_size) {
    const float* x    = (const float*)d_in[0];
    const int*   src  = (const int*)  d_in[1];
    const int*   dst  = (const int*)  d_in[2];
    const float* ea   = (const float*)d_in[3];
    const float* Wl1  = (const float*)d_in[4];
    const float* bl1  = (const float*)d_in[5];
    const float* Wr1  = (const float*)d_in[6];
    const float* br1  = (const float*)d_in[7];
    const float* We1  = (const float*)d_in[8];
    const float* att1 = (const float*)d_in[9];
    const float* b1   = (const float*)d_in[10];
    const float* Wl2  = (const float*)d_in[11];
    const float* bl2  = (const float*)d_in[12];
    const float* Wr2  = (const float*)d_in[13];
    const float* br2  = (const float*)d_in[14];
    const float* We2  = (const float*)d_in[15];
    const float* att2 = (const float*)d_in[16];
    const float* b2   = (const float*)d_in[17];
    float* out = (float*)d_out;

    float* h_ptr = nullptr;
    cudaGetSymbolAddress((void**)&h_ptr, g_h);

    const int T = 256;
    int gN   = (NN + T - 1) / T;
    int gN8  = (NN * 8 + T - 1) / T;      // float4 granularity over N*32
    int gE   = (EE + T - 1) / T;
    int gEw4 = (ET + 31) / 32;            // 4 edges/warp, 8 warps/block
    int gRow1 = (NN + 31) / 32;           // transform128: 32 rows/block
    int gRow2 = (NN + 7) / 8;             // transform32: 8 rows/block

    // self-loop mean edge_attr
    k_zero_cnt <<<gN, T>>>();
    k_accum_cnt<<<gE, T>>>(dst, ea);
    k_mean     <<<gN, T>>>();

    // ---- layer 1 ----
    k_transform128<<<gRow1, T>>>(x, Wl1, bl1, Wr1, br1);
    k_init_layer  <<<gN8, T>>>(h_ptr);
    k_scores      <<<gEw4, T>>>(src, dst, ea, We1, att1);
    k_aggregate   <<<gEw4, T>>>(src, dst, h_ptr);
    k_norm        <<<gN8, T>>>(h_ptr, b1);

    // ---- layer 2 (ReLU folded into transform read) ----
    k_transform32<<<gRow2, T>>>(Wl2, bl2, Wr2, br2);
    k_init_layer <<<gN8, T>>>(out);
    k_scores     <<<gEw4, T>>>(src, dst, ea, We2, att2);
    k_aggregate  <<<gEw4, T>>>(src, dst, out);
    k_norm       <<<gN8, T>>>(out, b2);
}